// round 10
// baseline (speedup 1.0000x reference)
#include <cuda_runtime.h>

#define BATCH   65536
#define NPLAYER 3
#define OBSD    48
#define TB      64
#define THREADS 512

// pitches (floats)
#define PHID 388
#define PENC 580
#define PH1  260

// smem float offsets (lifetime-overlapped)
// [0,16640):      hid (12416, stages 1a/1b) -> h1x2 (2x8320, stages 2/3)
// [16640,35200):  obs0 -> enc0 (18560, stage 1b/2) -> h2x2 (2x8192, stages 3/4)
// [35200,53760):  obs1 -> enc1 (18560) -> stage4 partials
// [53760,54532):  w3(768)+b3(3)
#define H1_OFF   0
#define HID_OFF  0
#define ENC0_OFF 16640
#define ENC1_OFF 35200
#define W3_OFF   53760
#define SMEM_FLOATS 54532

// packed weight buffer: per player 67072 float4s (layout unchanged from R9)
#define PK_PLAYER 67072
#define PK_TOTAL  (3 * PK_PLAYER)
#define PK_PI1    13824
#define PK_PI2    50688

__device__ float4 g_pk4[PK_TOTAL];

__device__ __forceinline__ float lrelu(float x) { return fmaxf(x, 0.01f * x); }

__device__ __forceinline__ unsigned f2tf(float x) {
    unsigned r;
    asm("cvt.rna.tf32.f32 %0, %1;" : "=r"(r) : "f"(x));
    return r;
}
__device__ __forceinline__ float tf32f(float x) { return __uint_as_float(f2tf(x)); }

__device__ __forceinline__ void mma_tf32(float d[4], unsigned a0, unsigned a1,
                                         unsigned a2, unsigned a3,
                                         unsigned b0, unsigned b1) {
    asm volatile(
        "mma.sync.aligned.m16n8k8.row.col.f32.tf32.tf32.f32 "
        "{%0,%1,%2,%3}, {%4,%5,%6,%7}, {%8,%9}, {%0,%1,%2,%3};"
        : "+f"(d[0]), "+f"(d[1]), "+f"(d[2]), "+f"(d[3])
        : "r"(a0), "r"(a1), "r"(a2), "r"(a3), "r"(b0), "r"(b1));
}

// =================== repack kernel (identical layout to R9) ===================
__global__ void repack_kernel(const float* __restrict__ prop_W2,
                              const float* __restrict__ ext_W2,
                              const float* __restrict__ opp_W2,
                              const float* __restrict__ pi_W1,
                              const float* __restrict__ pi_W2) {
    int idx = blockIdx.x * 256 + threadIdx.x;
    if (idx >= PK_TOTAL) return;
    int p = idx / PK_PLAYER;
    int r = idx - p * PK_PLAYER;
    float o[4];
    if (r < PK_PI1) {
        int pp = r / 4608, e = r - pp * 4608;
        int warp = e / 384, rem = e - warp * 384;
        int tp = rem >> 7, rem2 = rem & 127;
        int k8 = rem2 >> 5, lane = rem2 & 31;
        int gr = lane >> 2, gc = lane & 3;
        #pragma unroll
        for (int q = 0; q < 4; q++) {
            int t = tp * 2 + (q >> 1), b = q & 1;
            int c0 = warp * 48 + t * 8;
            int k = k8 * 8 + gc + b * 4;
            float s;
            if (pp == 0) {
                int head = c0 >> 6;
                s = prop_W2[((size_t)(p * 9 + head) * 32 + k) * 64 + (c0 & 63) + gr];
            } else if (pp == 1) {
                int head = (c0 >= 288) ? 1 : 0;
                s = ext_W2[((size_t)(p * 2 + head) * 32 + k) * 288 + c0 - head * 288 + gr];
            } else {
                s = opp_W2[((size_t)p * 32 + k) * 576 + c0 + gr];
            }
            o[q] = tf32f(s);
        }
    } else if (r < PK_PI2) {
        int e = r - PK_PI1;
        int lane = e & 31, t1 = e >> 5;
        int jp = t1 & 1, t2 = t1 >> 1;
        int nw = t2 & 7, t3 = t2 >> 3;
        int c = t3 % 36, h = t3 / 36;
        int gr = lane >> 2, gc = lane & 3;
        #pragma unroll
        for (int q = 0; q < 4; q++) {
            int j = jp * 2 + (q >> 1), b = q & 1;
            int k = h * 288 + c * 8 + gc + b * 4;
            int n = nw * 32 + j * 8 + gr;
            o[q] = tf32f(pi_W1[(size_t)p * 147456 + k * 256 + n]);
        }
    } else {
        int e = r - PK_PI2;
        int lane = e & 31, t1 = e >> 5;
        int jp = t1 & 1, t2 = t1 >> 1;
        int nw = t2 & 7, t3 = t2 >> 3;
        int c = t3 & 15, h = t3 >> 4;
        int gr = lane >> 2, gc = lane & 3;
        #pragma unroll
        for (int q = 0; q < 4; q++) {
            int j = jp * 2 + (q >> 1), b = q & 1;
            int k = h * 128 + c * 8 + gc + b * 4;
            int n = nw * 32 + j * 8 + gr;
            o[q] = tf32f(pi_W2[(size_t)p * 65536 + k * 256 + n]);
        }
    }
    g_pk4[idx] = make_float4(o[0], o[1], o[2], o[3]);
}

// =================== stage-1b pass (per tile, as R9) ===================
template<int HC, int NH, int ABASE, int MODE, int PPIDX>
__device__ __forceinline__ void enc_pass(const float* __restrict__ bias,
                                         const float* s_hid, float* s_enc,
                                         int warp, int lane, int p) {
    if (warp >= 12) return;
    const int gr = lane >> 2, gc = lane & 3;
    const int cw = warp * 48;
    const float4* pk = g_pk4 + (size_t)p * PK_PLAYER + PPIDX * 4608 + warp * 384 + lane;

    int headA[6];
    #pragma unroll
    for (int t = 0; t < 6; t++) {
        int c0 = cw + t * 8;
        headA[t] = (HC == 576) ? 0 : ((HC == 64) ? (c0 >> 6) : (c0 >= 288 ? 1 : 0));
    }

    float acc[6][2][4];
    #pragma unroll
    for (int t = 0; t < 6; t++)
        #pragma unroll
        for (int m = 0; m < 2; m++)
            #pragma unroll
            for (int u = 0; u < 4; u++) acc[t][m][u] = 0.f;

    float4 bv[3];
    #pragma unroll
    for (int tp = 0; tp < 3; tp++) bv[tp] = pk[tp * 4 * 32];

    #pragma unroll
    for (int k8 = 0; k8 < 4; k8++) {
        float4 nbv[3];
        if (k8 < 3) {
            #pragma unroll
            for (int tp = 0; tp < 3; tp++) nbv[tp] = pk[(tp * 4 + k8 + 1) * 32];
        }
        int cur = -1;
        unsigned a[2][4];
        #pragma unroll
        for (int t = 0; t < 6; t++) {
            if (headA[t] != cur) {
                cur = headA[t];
                int ac = ABASE + cur * 32 + k8 * 8 + gc;
                #pragma unroll
                for (int m = 0; m < 2; m++) {
                    int r = m * 16 + gr;
                    a[m][0] = __float_as_uint(s_hid[(r    ) * PHID + ac    ]);
                    a[m][1] = __float_as_uint(s_hid[(r + 8) * PHID + ac    ]);
                    a[m][2] = __float_as_uint(s_hid[(r    ) * PHID + ac + 4]);
                    a[m][3] = __float_as_uint(s_hid[(r + 8) * PHID + ac + 4]);
                }
            }
            unsigned b0 = __float_as_uint((t & 1) ? bv[t >> 1].z : bv[t >> 1].x);
            unsigned b1 = __float_as_uint((t & 1) ? bv[t >> 1].w : bv[t >> 1].y);
            mma_tf32(acc[t][0], a[0][0], a[0][1], a[0][2], a[0][3], b0, b1);
            mma_tf32(acc[t][1], a[1][0], a[1][1], a[1][2], a[1][3], b0, b1);
        }
        if (k8 < 3) {
            #pragma unroll
            for (int tp = 0; tp < 3; tp++) bv[tp] = nbv[tp];
        }
    }

    #pragma unroll
    for (int t = 0; t < 6; t++) {
        int cb = cw + t * 8 + 2 * gc;
        int head = headA[t];
        int cc = cb - head * HC;
        float b0 = bias[(p * NH + head) * HC + cc];
        float b1 = bias[(p * NH + head) * HC + cc + 1];
        #pragma unroll
        for (int m = 0; m < 2; m++) {
            int r = m * 16 + gr;
            float v00 = lrelu(acc[t][m][0] + b0), v01 = lrelu(acc[t][m][1] + b1);
            float v10 = lrelu(acc[t][m][2] + b0), v11 = lrelu(acc[t][m][3] + b1);
            float* e0 = &s_enc[(r    ) * PENC + cb];
            float* e1 = &s_enc[(r + 8) * PENC + cb];
            if (MODE == 0)      { e0[0] = v00; e0[1] = v01; e1[0] = v10; e1[1] = v11; }
            else if (MODE == 1) { e0[0] += v00; e0[1] += v01; e1[0] += v10; e1[1] += v11; }
            else {
                e0[0] = tf32f(e0[0] + v00); e0[1] = tf32f(e0[1] + v01);
                e1[0] = tf32f(e1[0] + v10); e1[1] = tf32f(e1[1] + v11);
            }
        }
    }
}

// =================== pi-head GEMM: 2 tiles share B; K-split; in-place reduction ===================
template<int KHALF, int NCH, int PKOFF, int PA, bool OUT_TF32>
__device__ __forceinline__ void pi_stage(const float* __restrict__ bias,
                                         const float* sA0, const float* sA1,
                                         float* out0, float* out1, int outPitch,
                                         int warp, int lane, int p) {
    const int h = warp >> 3, nw = warp & 7, n0 = nw * 32;
    const int gr = lane >> 2, gc = lane & 3;
    const float4* pk = g_pk4 + (size_t)p * PK_PLAYER + PKOFF
                     + ((size_t)h * NCH * 8 + nw) * 64 + lane;
    const int kbase = h * KHALF + gc;

    float acc[2][2][4][4];   // [tile][mtile][j][u]
    #pragma unroll
    for (int t = 0; t < 2; t++)
        #pragma unroll
        for (int m = 0; m < 2; m++)
            #pragma unroll
            for (int j = 0; j < 4; j++)
                #pragma unroll
                for (int u = 0; u < 4; u++) acc[t][m][j][u] = 0.f;

    float4 b0r[2], b1r[2];
    b0r[0] = pk[0];   b1r[0] = pk[32];
    b0r[1] = pk[512]; b1r[1] = pk[512 + 32];

    #pragma unroll 2
    for (int c = 0; c < NCH; c++) {
        float4 v0 = b0r[c & 1], v1 = b1r[c & 1];
        if (c + 2 < NCH) {
            b0r[c & 1] = pk[(c + 2) * 512];
            b1r[c & 1] = pk[(c + 2) * 512 + 32];
        }
        const int kg = kbase + c * 8;
        #pragma unroll
        for (int t = 0; t < 2; t++) {
            const float* sA = t ? sA1 : sA0;
            #pragma unroll
            for (int m = 0; m < 2; m++) {
                int r = m * 16 + gr;
                unsigned a0 = __float_as_uint(sA[(r    ) * PA + kg    ]);
                unsigned a1 = __float_as_uint(sA[(r + 8) * PA + kg    ]);
                unsigned a2 = __float_as_uint(sA[(r    ) * PA + kg + 4]);
                unsigned a3 = __float_as_uint(sA[(r + 8) * PA + kg + 4]);
                mma_tf32(acc[t][m][0], a0, a1, a2, a3,
                         __float_as_uint(v0.x), __float_as_uint(v0.y));
                mma_tf32(acc[t][m][1], a0, a1, a2, a3,
                         __float_as_uint(v0.z), __float_as_uint(v0.w));
                mma_tf32(acc[t][m][2], a0, a1, a2, a3,
                         __float_as_uint(v1.x), __float_as_uint(v1.y));
                mma_tf32(acc[t][m][3], a0, a1, a2, a3,
                         __float_as_uint(v1.z), __float_as_uint(v1.w));
            }
        }
    }

    // K-split reduction IN-PLACE in output buffers: h=1 writes raw partials,
    // sync, h=0 adds own partials + bias, finalizes.
    if (h == 1) {
        #pragma unroll
        for (int t = 0; t < 2; t++) {
            float* outp = t ? out1 : out0;
            #pragma unroll
            for (int m = 0; m < 2; m++) {
                int r = m * 16 + gr;
                #pragma unroll
                for (int j = 0; j < 4; j++) {
                    int cA = n0 + j * 8 + 2 * gc;
                    outp[(r    ) * outPitch + cA    ] = acc[t][m][j][0];
                    outp[(r    ) * outPitch + cA + 1] = acc[t][m][j][1];
                    outp[(r + 8) * outPitch + cA    ] = acc[t][m][j][2];
                    outp[(r + 8) * outPitch + cA + 1] = acc[t][m][j][3];
                }
            }
        }
    }
    __syncthreads();
    if (h == 0) {
        #pragma unroll
        for (int t = 0; t < 2; t++) {
            float* outp = t ? out1 : out0;
            #pragma unroll
            for (int m = 0; m < 2; m++) {
                int r = m * 16 + gr;
                #pragma unroll
                for (int j = 0; j < 4; j++) {
                    int cA = n0 + j * 8 + 2 * gc;
                    float b0 = bias[cA], b1 = bias[cA + 1];
                    float v00 = lrelu(acc[t][m][j][0] + outp[(r    ) * outPitch + cA    ] + b0);
                    float v01 = lrelu(acc[t][m][j][1] + outp[(r    ) * outPitch + cA + 1] + b1);
                    float v10 = lrelu(acc[t][m][j][2] + outp[(r + 8) * outPitch + cA    ] + b0);
                    float v11 = lrelu(acc[t][m][j][3] + outp[(r + 8) * outPitch + cA + 1] + b1);
                    if (OUT_TF32) { v00 = tf32f(v00); v01 = tf32f(v01); v10 = tf32f(v10); v11 = tf32f(v11); }
                    outp[(r    ) * outPitch + cA    ] = v00;
                    outp[(r    ) * outPitch + cA + 1] = v01;
                    outp[(r + 8) * outPitch + cA    ] = v10;
                    outp[(r + 8) * outPitch + cA + 1] = v11;
                }
            }
        }
    }
}

// =================== stage 1a (per tile) ===================
__device__ __forceinline__ void stage1a(const float* s_obs, float* s_hid,
    const float* __restrict__ prop_W1, const float* __restrict__ prop_b1,
    const float* __restrict__ ext_W1,  const float* __restrict__ ext_b1,
    const float* __restrict__ opp_W1,  const float* __restrict__ opp_b1,
    int p, int tid) {
    for (int i = tid; i < 32 * 288; i += THREADS) {
        int r = i / 288, rest = i - r * 288, n = rest >> 5, j = rest & 31;
        const float* w = prop_W1 + ((p * 9 + n) * 2) * 32 + j;
        float h = s_obs[r * OBSD + 2 * n] * w[0]
                + s_obs[r * OBSD + 2 * n + 1] * w[32]
                + prop_b1[(p * 9 + n) * 32 + j];
        s_hid[r * PHID + n * 32 + j] = tf32f(lrelu(h));
    }
    for (int i = tid; i < 32 * 64; i += THREADS) {
        int r = i >> 6, rest = i & 63, n = rest >> 5, j = rest & 31;
        const float* w = ext_W1 + ((p * 2 + n) * 6) * 32 + j;
        float h = ext_b1[(p * 2 + n) * 32 + j];
        #pragma unroll
        for (int q = 0; q < 6; q++) h += s_obs[r * OBSD + 18 + n * 6 + q] * w[q * 32];
        s_hid[r * PHID + 288 + n * 32 + j] = tf32f(lrelu(h));
    }
    for (int i = tid; i < 32 * 32; i += THREADS) {
        int r = i >> 5, j = i & 31;
        const float* w = opp_W1 + (p * 18) * 32 + j;
        float h = opp_b1[p * 32 + j];
        #pragma unroll
        for (int q = 0; q < 18; q++) h += s_obs[r * OBSD + 30 + q] * w[q * 32];
        s_hid[r * PHID + 352 + j] = tf32f(lrelu(h));
    }
}

__global__ __launch_bounds__(THREADS, 1)
void mlpac_kernel(
    const float* __restrict__ obs,
    const float* __restrict__ prop_W1, const float* __restrict__ prop_b1,
    const float* __restrict__ prop_b2,
    const float* __restrict__ ext_W1,  const float* __restrict__ ext_b1,
    const float* __restrict__ ext_b2,
    const float* __restrict__ opp_W1,  const float* __restrict__ opp_b1,
    const float* __restrict__ opp_b2,
    const float* __restrict__ pi_b1,   const float* __restrict__ pi_b2,
    const float* __restrict__ pi_W3,   const float* __restrict__ pi_b3,
    float* __restrict__ out)
{
    extern __shared__ float sm[];
    float* s_hid  = sm + HID_OFF;
    float* s_enc0 = sm + ENC0_OFF;
    float* s_enc1 = sm + ENC1_OFF;
    float* s_h1_0 = sm + H1_OFF;            // pitch PH1
    float* s_h1_1 = sm + H1_OFF + 8320;
    float* s_h2_0 = sm + ENC0_OFF;          // pitch 256 (enc0 dead in stage3)
    float* s_h2_1 = sm + ENC0_OFF + 8192;
    float* s_w3   = sm + W3_OFF;
    float* s_part = sm + ENC1_OFF;          // stage4 partials (enc1 dead)

    const int tid  = threadIdx.x;
    const int warp = tid >> 5, lane = tid & 31;
    const int p    = blockIdx.y;
    const int b0   = blockIdx.x * TB;

    // ---------------- stage 0: obs for both tiles + w3 ----------------
    for (int g = tid; g < TB * (OBSD / 4); g += THREADS) {
        int r = g / 12, q = g - r * 12;
        float* dst = (r < 32) ? &s_enc0[r * OBSD] : &s_enc1[(r - 32) * OBSD];
        *(float4*)&dst[q * 4] =
            *(const float4*)&obs[((size_t)(b0 + r) * NPLAYER + p) * OBSD + q * 4];
    }
    for (int g = tid; g < 768; g += THREADS) s_w3[g] = pi_W3[(size_t)p * 768 + g];
    if (tid < 3) s_w3[768 + tid] = pi_b3[p * 3 + tid];
    __syncthreads();

    // ---------------- tile 0: 1a + 1b ----------------
    stage1a(s_enc0 /*obs0*/, s_hid, prop_W1, prop_b1, ext_W1, ext_b1,
            opp_W1, opp_b1, p, tid);
    __syncthreads();
    enc_pass<64,  9, 0,   0, 0>(prop_b2, s_hid, s_enc0, warp, lane, p);
    enc_pass<288, 2, 288, 1, 1>(ext_b2,  s_hid, s_enc0, warp, lane, p);
    enc_pass<576, 1, 352, 2, 2>(opp_b2,  s_hid, s_enc0, warp, lane, p);
    __syncthreads();

    // ---------------- tile 1: 1a + 1b ----------------
    stage1a(s_enc1 /*obs1*/, s_hid, prop_W1, prop_b1, ext_W1, ext_b1,
            opp_W1, opp_b1, p, tid);
    __syncthreads();
    enc_pass<64,  9, 0,   0, 0>(prop_b2, s_hid, s_enc1, warp, lane, p);
    enc_pass<288, 2, 288, 1, 1>(ext_b2,  s_hid, s_enc1, warp, lane, p);
    enc_pass<576, 1, 352, 2, 2>(opp_b2,  s_hid, s_enc1, warp, lane, p);
    __syncthreads();

    // ---------------- stage 2: h1 = lrelu(enc @ pi_W1 + b1), both tiles ----------------
    pi_stage<288, 36, PK_PI1, PENC, true>(pi_b1 + p * 256, s_enc0, s_enc1,
                                          s_h1_0, s_h1_1, PH1, warp, lane, p);
    __syncthreads();

    // ---------------- stage 3: h2 = lrelu(h1 @ pi_W2 + b2), both tiles ----------------
    pi_stage<128, 16, PK_PI2, PH1, false>(pi_b2 + p * 256, s_h1_0, s_h1_1,
                                          s_h2_0, s_h2_1, 256, warp, lane, p);
    __syncthreads();

    // ---------------- stage 4: out = tanh(h2 @ pi_W3 + b3), per tile ----------------
    #pragma unroll
    for (int t = 0; t < 2; t++) {
        const float* h2b = t ? s_h2_1 : s_h2_0;
        if (tid < 384) {
            int q = tid & 3, a = (tid >> 2) % 3, r = tid / 12;
            float s = 0.f;
            const float* h2 = &h2b[r * 256 + q * 64];
            const float* w3 = &s_w3[q * 64 * 3 + a];
            #pragma unroll 16
            for (int i = 0; i < 64; i++) s += h2[i] * w3[i * 3];
            s_part[tid] = s;
        }
        __syncthreads();
        if (tid < 96) {
            int r = tid / 3, a = tid % 3;
            int base = (r * 3 + a) * 4;
            float s = s_w3[768 + a] + s_part[base] + s_part[base + 1]
                    + s_part[base + 2] + s_part[base + 3];
            out[((size_t)(b0 + t * 32 + r) * NPLAYER + p) * 3 + a] = tanhf(s);
        }
        __syncthreads();
    }
}

extern "C" void kernel_launch(void* const* d_in, const int* in_sizes, int n_in,
                              void* d_out, int out_size)
{
    (void)in_sizes; (void)n_in; (void)out_size;
    const float* obs     = (const float*)d_in[0];
    const float* prop_W1 = (const float*)d_in[1];
    const float* prop_b1 = (const float*)d_in[2];
    const float* prop_W2 = (const float*)d_in[3];
    const float* prop_b2 = (const float*)d_in[4];
    const float* ext_W1  = (const float*)d_in[5];
    const float* ext_b1  = (const float*)d_in[6];
    const float* ext_W2  = (const float*)d_in[7];
    const float* ext_b2  = (const float*)d_in[8];
    const float* opp_W1  = (const float*)d_in[9];
    const float* opp_b1  = (const float*)d_in[10];
    const float* opp_W2  = (const float*)d_in[11];
    const float* opp_b2  = (const float*)d_in[12];
    const float* pi_W1   = (const float*)d_in[13];
    const float* pi_b1   = (const float*)d_in[14];
    const float* pi_W2   = (const float*)d_in[15];
    const float* pi_b2   = (const float*)d_in[16];
    const float* pi_W3   = (const float*)d_in[17];
    const float* pi_b3   = (const float*)d_in[18];
    float* out = (float*)d_out;

    repack_kernel<<<(PK_TOTAL + 255) / 256, 256>>>(prop_W2, ext_W2, opp_W2, pi_W1, pi_W2);

    const int smem_bytes = SMEM_FLOATS * sizeof(float);
    cudaFuncSetAttribute(mlpac_kernel, cudaFuncAttributeMaxDynamicSharedMemorySize, smem_bytes);

    dim3 grid(BATCH / TB, NPLAYER);
    mlpac_kernel<<<grid, THREADS, smem_bytes>>>(
        obs, prop_W1, prop_b1, prop_b2,
        ext_W1, ext_b1, ext_b2,
        opp_W1, opp_b1, opp_b2,
        pi_b1, pi_b2, pi_W3, pi_b3, out);
}

// round 12
// speedup vs baseline: 2.1080x; 2.1080x over previous
#include <cuda_runtime.h>
#include <cuda_fp16.h>

#define BATCH   65536
#define NPLAYER 3
#define OBSD    48
#define TB      32
#define THREADS 256

// pitches in 32-bit words (all %32==4 -> conflict-free fragment access)
#define PHIDW 196   // hid fp16: 192 words (384 halves)
#define PE16W 292   // enc fp16: 288 words (576 halves)
#define PH1W  132   // h1 fp16: 128 words (256 halves)
#define PH2   260   // h2 fp32: 256 cols

// smem word offsets (lifetime-overlapped)
// [0,6272):      hid (32*196) -> h1 (32*132) -> stage4 partials
// [6272,15616):  obs(48/row) -> enc fp16 (32*292) -> h2 fp32 (32*260)
// [15616,16388): w3(768)+b3(3)
#define HID_OFF  0
#define EF16_OFF 6272
#define W3_OFF   15616
#define SMEM_WORDS 16388

// packed fp16 weights (float4 = 4 x b32, each b32 = half2 (k,k+1))
//   enc: 3 passes x (8 warps x 2 chunks x 5 t x 32 lanes) = 7680
//   pi1: 36c x (8nw x 2jp x 32) = 18432
//   pi2: 16c x (8nw x 2jp x 32) = 8192
#define PKP_ENC 0
#define PKP_PI1 7680
#define PKP_PI2 26112
#define PK_PLAYER 34304
#define PK_TOTAL (3 * PK_PLAYER)

__device__ float4 g_pk4[PK_TOTAL];

__device__ __forceinline__ float lrelu(float x) { return fmaxf(x, 0.01f * x); }

__device__ __forceinline__ unsigned pack_h2(float a, float b) {
    __half2 h = __floats2half2_rn(a, b);
    return *reinterpret_cast<unsigned*>(&h);
}

__device__ __forceinline__ void mma_f16(float d[4], unsigned a0, unsigned a1,
                                        unsigned a2, unsigned a3,
                                        unsigned b0, unsigned b1) {
    asm volatile(
        "mma.sync.aligned.m16n8k16.row.col.f32.f16.f16.f32 "
        "{%0,%1,%2,%3}, {%4,%5,%6,%7}, {%8,%9}, {%0,%1,%2,%3};"
        : "+f"(d[0]), "+f"(d[1]), "+f"(d[2]), "+f"(d[3])
        : "r"(a0), "r"(a1), "r"(a2), "r"(a3), "r"(b0), "r"(b1));
}

// =================== repack: fp16 fragment-order weights ===================
__global__ void repack_kernel(const float* __restrict__ prop_W2,
                              const float* __restrict__ ext_W2,
                              const float* __restrict__ opp_W2,
                              const float* __restrict__ pi_W1,
                              const float* __restrict__ pi_W2) {
    int idx = blockIdx.x * 256 + threadIdx.x;
    if (idx >= PK_TOTAL) return;
    int p = idx / PK_PLAYER;
    int r = idx - p * PK_PLAYER;
    unsigned o[4];
    if (r < PKP_PI1) {
        // enc: pass*2560 + warp*320 + c*160 + t*32 + lane ; t covers j = 2t, 2t+1
        int pass = r / 2560, e = r - pass * 2560;
        int warp = e / 320, e2 = e - warp * 320;
        int c = e2 / 160, e3 = e2 - c * 160;
        int t = e3 >> 5, lane = e3 & 31;
        int gr = lane >> 2, gc = lane & 3;
        #pragma unroll
        for (int q = 0; q < 4; q++) {
            int j = t * 2 + (q >> 1), b = q & 1;
            if (j > 8) { o[q] = 0; continue; }
            int col = warp * 72 + j * 8 + gr;           // 0..575
            int k = c * 16 + 2 * gc + b * 8;            // 0..31 (pair k,k+1)
            float w0, w1;
            if (pass == 0) {
                int head = col >> 6, cc = col & 63;
                const float* W = prop_W2 + ((size_t)(p * 9 + head) * 32) * 64 + cc;
                w0 = W[(size_t)k * 64]; w1 = W[(size_t)(k + 1) * 64];
            } else if (pass == 1) {
                int head = (col >= 288) ? 1 : 0, cc = col - head * 288;
                const float* W = ext_W2 + ((size_t)(p * 2 + head) * 32) * 288 + cc;
                w0 = W[(size_t)k * 288]; w1 = W[(size_t)(k + 1) * 288];
            } else {
                const float* W = opp_W2 + ((size_t)p * 32) * 576 + col;
                w0 = W[(size_t)k * 576]; w1 = W[(size_t)(k + 1) * 576];
            }
            o[q] = pack_h2(w0, w1);
        }
    } else {
        int base;
        const float* W;
        if (r < PKP_PI2) { base = r - PKP_PI1; W = pi_W1 + (size_t)p * 147456; }
        else             { base = r - PKP_PI2; W = pi_W2 + (size_t)p * 65536; }
        int c = base / 512, e2 = base - c * 512;
        int nw = e2 >> 6, e3 = e2 & 63;
        int jp = e3 >> 5, lane = e3 & 31;
        int gr = lane >> 2, gc = lane & 3;
        #pragma unroll
        for (int q = 0; q < 4; q++) {
            int j = jp * 2 + (q >> 1), b = q & 1;
            int k = c * 16 + 2 * gc + b * 8;
            int n = nw * 32 + j * 8 + gr;
            o[q] = pack_h2(W[(size_t)k * 256 + n], W[(size_t)(k + 1) * 256 + n]);
        }
    }
    g_pk4[idx] = make_float4(__uint_as_float(o[0]), __uint_as_float(o[1]),
                             __uint_as_float(o[2]), __uint_as_float(o[3]));
}

// =================== stage-1b fused: per j-tile, 3 passes in registers ===================
__device__ __forceinline__ void enc_all(const float* __restrict__ prop_b2,
                                        const float* __restrict__ ext_b2,
                                        const float* __restrict__ opp_b2,
                                        const float* smw, float* ef16,
                                        int warp, int lane, int p) {
    const int gr = lane >> 2, gc = lane & 3;
    const int cw = warp * 72;
    const float4* pk = g_pk4 + (size_t)p * PK_PLAYER + PKP_ENC + warp * 320 + lane;

    #pragma unroll
    for (int j = 0; j < 9; j++) {
        const int c0 = cw + j * 8;
        const int cb = c0 + 2 * gc;   // even column of this thread's pair
        float sum[2][4];
        #pragma unroll
        for (int m = 0; m < 2; m++)
            #pragma unroll
            for (int u = 0; u < 4; u++) sum[m][u] = 0.f;

        #pragma unroll
        for (int pass = 0; pass < 3; pass++) {
            int abase, bidx0;
            if (pass == 0) { int head = c0 >> 6; abase = head * 16;
                             bidx0 = (p * 9 + head) * 64 + (cb & 63); }
            else if (pass == 1) { int head = (c0 >= 288) ? 1 : 0; abase = 144 + head * 16;
                             bidx0 = (p * 2 + head) * 288 + cb - head * 288; }
            else { abase = 176; bidx0 = p * 576 + cb; }
            const float* bias = (pass == 0) ? prop_b2 : (pass == 1) ? ext_b2 : opp_b2;

            float acc[2][4];
            #pragma unroll
            for (int m = 0; m < 2; m++)
                #pragma unroll
                for (int u = 0; u < 4; u++) acc[m][u] = 0.f;

            #pragma unroll
            for (int c = 0; c < 2; c++) {
                int ac = abase + c * 8 + gc;
                unsigned a[2][4];
                #pragma unroll
                for (int m = 0; m < 2; m++) {
                    int rr = m * 16 + gr;
                    a[m][0] = __float_as_uint(smw[(rr    ) * PHIDW + ac    ]);
                    a[m][1] = __float_as_uint(smw[(rr + 8) * PHIDW + ac    ]);
                    a[m][2] = __float_as_uint(smw[(rr    ) * PHIDW + ac + 4]);
                    a[m][3] = __float_as_uint(smw[(rr + 8) * PHIDW + ac + 4]);
                }
                float4 v = pk[pass * 2560 + c * 160 + (j >> 1) * 32];
                unsigned b0 = __float_as_uint((j & 1) ? v.z : v.x);
                unsigned b1 = __float_as_uint((j & 1) ? v.w : v.y);
                mma_f16(acc[0], a[0][0], a[0][1], a[0][2], a[0][3], b0, b1);
                mma_f16(acc[1], a[1][0], a[1][1], a[1][2], a[1][3], b0, b1);
            }
            float b0f = bias[bidx0], b1f = bias[bidx0 + 1];
            #pragma unroll
            for (int m = 0; m < 2; m++) {
                sum[m][0] += lrelu(acc[m][0] + b0f);
                sum[m][1] += lrelu(acc[m][1] + b1f);
                sum[m][2] += lrelu(acc[m][2] + b0f);
                sum[m][3] += lrelu(acc[m][3] + b1f);
            }
        }
        const int wc = (c0 >> 1) + gc;   // word index of halves (cb, cb+1)
        #pragma unroll
        for (int m = 0; m < 2; m++) {
            int rr = m * 16 + gr;
            ef16[(rr    ) * PE16W + wc] = __uint_as_float(pack_h2(sum[m][0], sum[m][1]));
            ef16[(rr + 8) * PE16W + wc] = __uint_as_float(pack_h2(sum[m][2], sum[m][3]));
        }
    }
}

// =================== pi GEMM: 8 n-warps, full K, fp16 mma, depth-2 prefetch ===================
// OUTMODE 0: fp16 words (h1); 1: fp32 scalars (h2)
template<int NCH, int PKOFF, int PAW, int OUTMODE>
__device__ __forceinline__ void pi_stage(const float* __restrict__ bias,
                                         const float* sAw, float* outp, int outPitch,
                                         int warp, int lane, int p) {
    const int n0 = warp * 32;
    const int gr = lane >> 2, gc = lane & 3;
    const float4* pk = g_pk4 + (size_t)p * PK_PLAYER + PKOFF + warp * 64 + lane;

    float acc[2][4][4];
    #pragma unroll
    for (int m = 0; m < 2; m++)
        #pragma unroll
        for (int j = 0; j < 4; j++)
            #pragma unroll
            for (int u = 0; u < 4; u++) acc[m][j][u] = 0.f;

    float4 b0r[2], b1r[2];
    b0r[0] = pk[0];   b1r[0] = pk[32];
    b0r[1] = pk[512]; b1r[1] = pk[512 + 32];

    #pragma unroll 4
    for (int c = 0; c < NCH; c++) {
        float4 v0 = b0r[c & 1], v1 = b1r[c & 1];
        if (c + 2 < NCH) {
            b0r[c & 1] = pk[(c + 2) * 512];
            b1r[c & 1] = pk[(c + 2) * 512 + 32];
        }
        const int kg = c * 8 + gc;
        unsigned a[2][4];
        #pragma unroll
        for (int m = 0; m < 2; m++) {
            int rr = m * 16 + gr;
            a[m][0] = __float_as_uint(sAw[(rr    ) * PAW + kg    ]);
            a[m][1] = __float_as_uint(sAw[(rr + 8) * PAW + kg    ]);
            a[m][2] = __float_as_uint(sAw[(rr    ) * PAW + kg + 4]);
            a[m][3] = __float_as_uint(sAw[(rr + 8) * PAW + kg + 4]);
        }
        #pragma unroll
        for (int m = 0; m < 2; m++) {
            mma_f16(acc[m][0], a[m][0], a[m][1], a[m][2], a[m][3],
                    __float_as_uint(v0.x), __float_as_uint(v0.y));
            mma_f16(acc[m][1], a[m][0], a[m][1], a[m][2], a[m][3],
                    __float_as_uint(v0.z), __float_as_uint(v0.w));
            mma_f16(acc[m][2], a[m][0], a[m][1], a[m][2], a[m][3],
                    __float_as_uint(v1.x), __float_as_uint(v1.y));
            mma_f16(acc[m][3], a[m][0], a[m][1], a[m][2], a[m][3],
                    __float_as_uint(v1.z), __float_as_uint(v1.w));
        }
    }

    #pragma unroll
    for (int m = 0; m < 2; m++) {
        int rr = m * 16 + gr;
        #pragma unroll
        for (int j = 0; j < 4; j++) {
            int cA = n0 + j * 8 + 2 * gc;   // even
            float b0 = bias[cA], b1 = bias[cA + 1];
            float v00 = lrelu(acc[m][j][0] + b0), v01 = lrelu(acc[m][j][1] + b1);
            float v10 = lrelu(acc[m][j][2] + b0), v11 = lrelu(acc[m][j][3] + b1);
            if (OUTMODE == 0) {
                int wc = cA >> 1;
                outp[(rr    ) * outPitch + wc] = __uint_as_float(pack_h2(v00, v01));
                outp[(rr + 8) * outPitch + wc] = __uint_as_float(pack_h2(v10, v11));
            } else {
                outp[(rr    ) * outPitch + cA    ] = v00;
                outp[(rr    ) * outPitch + cA + 1] = v01;
                outp[(rr + 8) * outPitch + cA    ] = v10;
                outp[(rr + 8) * outPitch + cA + 1] = v11;
            }
        }
    }
}

__global__ __launch_bounds__(THREADS, 2)
void mlpac_kernel(
    const float* __restrict__ obs,
    const float* __restrict__ prop_W1, const float* __restrict__ prop_b1,
    const float* __restrict__ prop_b2,
    const float* __restrict__ ext_W1,  const float* __restrict__ ext_b1,
    const float* __restrict__ ext_b2,
    const float* __restrict__ opp_W1,  const float* __restrict__ opp_b1,
    const float* __restrict__ opp_b2,
    const float* __restrict__ pi_b1,   const float* __restrict__ pi_b2,
    const float* __restrict__ pi_W3,   const float* __restrict__ pi_b3,
    float* __restrict__ out)
{
    extern __shared__ float sm[];
    float* s_hid  = sm + HID_OFF;    // fp16 words, pitch PHIDW (stages 1a/1b)
    float* s_ef16 = sm + EF16_OFF;   // fp16 words, pitch PE16W (stage 1b out / 2 in)
    float* s_obs  = s_ef16;          // obs staged here (dead before 1b writes? see below)
    float* s_h1   = sm + HID_OFF;    // fp16 words, pitch PH1W (hid dead after 1b)
    float* s_h2   = sm + EF16_OFF;   // fp32, pitch PH2 (ef16 dead after stage 2)
    float* s_w3   = sm + W3_OFF;
    float* s_part = sm + HID_OFF;    // stage4 partials (h1 dead)

    const int tid  = threadIdx.x;
    const int warp = tid >> 5, lane = tid & 31;
    const int p    = blockIdx.y;
    const int b0   = blockIdx.x * TB;

    // ---------------- stage 0: obs + w3 ----------------
    // obs lives in the ef16 region rows: row r words [r*PE16W, r*PE16W+48)
    for (int g = tid; g < TB * (OBSD / 4); g += THREADS) {
        int r = g / 12, q = g - r * 12;
        *(float4*)&s_obs[r * PE16W + q * 4] =
            *(const float4*)&obs[((size_t)(b0 + r) * NPLAYER + p) * OBSD + q * 4];
    }
    for (int g = tid; g < 768; g += THREADS) s_w3[g] = pi_W3[(size_t)p * 768 + g];
    if (tid < 3) s_w3[768 + tid] = pi_b3[p * 3 + tid];
    __syncthreads();

    // ---------------- stage 1a: hidden layers -> fp16 words in s_hid ----------------
    for (int i = tid; i < 32 * 9 * 16; i += THREADS) {
        int r = i / 144, rest = i - r * 144, n = rest >> 4, jw = rest & 15;
        const float* w = prop_W1 + ((p * 9 + n) * 2) * 32 + 2 * jw;
        float o0 = s_obs[r * PE16W + 2 * n], o1 = s_obs[r * PE16W + 2 * n + 1];
        const float* bb = prop_b1 + (p * 9 + n) * 32 + 2 * jw;
        float v0 = lrelu(o0 * w[0] + o1 * w[32] + bb[0]);
        float v1 = lrelu(o0 * w[1] + o1 * w[33] + bb[1]);
        s_hid[r * PHIDW + n * 16 + jw] = __uint_as_float(pack_h2(v0, v1));
    }
    for (int i = tid; i < 32 * 2 * 16; i += THREADS) {
        int r = i >> 5, rest = i & 31, n = rest >> 4, jw = rest & 15;
        const float* w = ext_W1 + ((p * 2 + n) * 6) * 32 + 2 * jw;
        const float* bb = ext_b1 + (p * 2 + n) * 32 + 2 * jw;
        float v0 = bb[0], v1 = bb[1];
        #pragma unroll
        for (int q = 0; q < 6; q++) {
            float o = s_obs[r * PE16W + 18 + n * 6 + q];
            v0 += o * w[q * 32]; v1 += o * w[q * 32 + 1];
        }
        s_hid[r * PHIDW + 144 + n * 16 + jw] = __uint_as_float(pack_h2(lrelu(v0), lrelu(v1)));
    }
    for (int i = tid; i < 32 * 16; i += THREADS) {
        int r = i >> 4, jw = i & 15;
        const float* w = opp_W1 + (p * 18) * 32 + 2 * jw;
        const float* bb = opp_b1 + p * 32 + 2 * jw;
        float v0 = bb[0], v1 = bb[1];
        #pragma unroll
        for (int q = 0; q < 18; q++) {
            float o = s_obs[r * PE16W + 30 + q];
            v0 += o * w[q * 32]; v1 += o * w[q * 32 + 1];
        }
        s_hid[r * PHIDW + 176 + jw] = __uint_as_float(pack_h2(lrelu(v0), lrelu(v1)));
    }
    __syncthreads();   // hid ready; obs (in ef16 region) now dead -> ef16 writable

    // ---------------- stage 1b: enc = sum of 3 branch layers (fused, registers) ----------------
    enc_all(prop_b2, ext_b2, opp_b2, s_hid, s_ef16, warp, lane, p);
    __syncthreads();   // ef16 ready; hid dead

    // ---------------- stage 2: h1 = lrelu(enc @ pi_W1 + b1) ----------------
    pi_stage<36, PKP_PI1, PE16W, 0>(pi_b1 + p * 256, s_ef16, s_h1, PH1W, warp, lane, p);
    __syncthreads();   // h1 ready; ef16 dead

    // ---------------- stage 3: h2 = lrelu(h1 @ pi_W2 + b2) ----------------
    pi_stage<16, PKP_PI2, PH1W, 1>(pi_b2 + p * 256, s_h1, s_h2, PH2, warp, lane, p);
    __syncthreads();   // h2 ready; h1 dead

    // ---------------- stage 4: out = tanh(h2 @ pi_W3 + b3), 2-way split ----------------
    if (tid < 192) {
        int r = tid / 6, rem = tid % 6, a = rem >> 1, q = rem & 1;
        float s = 0.f;
        const float* h2 = &s_h2[r * PH2 + q * 128];
        const float* w3 = &s_w3[q * 128 * 3 + a];
        #pragma unroll 16
        for (int i = 0; i < 128; i++) s += h2[i] * w3[i * 3];
        s_part[tid] = s;
    }
    __syncthreads();
    if (tid < 96) {
        int r = tid / 3, a = tid % 3;
        float s = s_w3[768 + a] + s_part[r * 6 + a * 2] + s_part[r * 6 + a * 2 + 1];
        out[((size_t)(b0 + r) * NPLAYER + p) * 3 + a] = tanhf(s);
    }
}

extern "C" void kernel_launch(void* const* d_in, const int* in_sizes, int n_in,
                              void* d_out, int out_size)
{
    (void)in_sizes; (void)n_in; (void)out_size;
    const float* obs     = (const float*)d_in[0];
    const float* prop_W1 = (const float*)d_in[1];
    const float* prop_b1 = (const float*)d_in[2];
    const float* prop_W2 = (const float*)d_in[3];
    const float* prop_b2 = (const float*)d_in[4];
    const float* ext_W1  = (const float*)d_in[5];
    const float* ext_b1  = (const float*)d_in[6];
    const float* ext_W2  = (const float*)d_in[7];
    const float* ext_b2  = (const float*)d_in[8];
    const float* opp_W1  = (const float*)d_in[9];
    const float* opp_b1  = (const float*)d_in[10];
    const float* opp_W2  = (const float*)d_in[11];
    const float* opp_b2  = (const float*)d_in[12];
    const float* pi_W1   = (const float*)d_in[13];
    const float* pi_b1   = (const float*)d_in[14];
    const float* pi_W2   = (const float*)d_in[15];
    const float* pi_b2   = (const float*)d_in[16];
    const float* pi_W3   = (const float*)d_in[17];
    const float* pi_b3   = (const float*)d_in[18];
    float* out = (float*)d_out;

    repack_kernel<<<(PK_TOTAL + 255) / 256, 256>>>(prop_W2, ext_W2, opp_W2, pi_W1, pi_W2);

    const int smem_bytes = SMEM_WORDS * sizeof(float);
    cudaFuncSetAttribute(mlpac_kernel, cudaFuncAttributeMaxDynamicSharedMemorySize, smem_bytes);

    dim3 grid(BATCH / TB, NPLAYER);
    mlpac_kernel<<<grid, THREADS, smem_bytes>>>(
        obs, prop_W1, prop_b1, prop_b2,
        ext_W1, ext_b1, ext_b2,
        opp_W1, opp_b1, opp_b2,
        pi_b1, pi_b2, pi_W3, pi_b3, out);
}

// round 13
// speedup vs baseline: 2.7052x; 1.2833x over previous
#include <cuda_runtime.h>
#include <cuda_fp16.h>

#define BATCH   65536
#define NPLAYER 3
#define OBSD    48
#define TB      32
#define THREADS 256

// pitches in 32-bit words (all %32==4 -> conflict-free LDS/LDSM phases)
#define PHIDW 196   // hid fp16: 192 words (384 halves)
#define PE16W 292   // enc fp16: 288 words (576 halves)
#define PH1W  132   // h1/h2 fp16: 128 words (256 halves)

// smem word offsets (lifetime-overlapped)
// [0,6272):      hid (32*196) -> h1 fp16 (32*132)
// [6272,15616):  obs(48/row, pitch PE16W) -> enc fp16 (32*292) -> h2 fp16 (32*132)
#define HID_OFF  0
#define EF16_OFF 6272
#define SMEM_WORDS 15616

// packed fp16 weights (float4 = 4 x b32, each b32 = half2 (k,k+1))
//   enc: 3 passes x (8 warps x 2 chunks x 5 t x 32 lanes) = 7680
//   pi1: 36c x (8nw x 2jp x 32) = 18432
//   pi2: 16c x (8nw x 2jp x 32) = 8192
//   pi3: 8 cpair x 32 = 256
#define PKP_ENC 0
#define PKP_PI1 7680
#define PKP_PI2 26112
#define PKP_PI3 34304
#define PK_PLAYER 34560
#define PK_TOTAL (3 * PK_PLAYER)

__device__ float4 g_pk4[PK_TOTAL];

__device__ __forceinline__ float lrelu(float x) { return fmaxf(x, 0.01f * x); }

__device__ __forceinline__ unsigned pack_h2(float a, float b) {
    __half2 h = __floats2half2_rn(a, b);
    return *reinterpret_cast<unsigned*>(&h);
}

__device__ __forceinline__ unsigned s2u(const void* p) {
    return (unsigned)__cvta_generic_to_shared(p);
}

#define LDSM4(a, addr) \
    asm volatile("ldmatrix.sync.aligned.m8n8.x4.shared.b16 {%0,%1,%2,%3}, [%4];" \
        : "=r"((a)[0]), "=r"((a)[1]), "=r"((a)[2]), "=r"((a)[3]) : "r"(addr))

__device__ __forceinline__ void mma_f16(float d[4], const unsigned a[4],
                                        unsigned b0, unsigned b1) {
    asm volatile(
        "mma.sync.aligned.m16n8k16.row.col.f32.f16.f16.f32 "
        "{%0,%1,%2,%3}, {%4,%5,%6,%7}, {%8,%9}, {%0,%1,%2,%3};"
        : "+f"(d[0]), "+f"(d[1]), "+f"(d[2]), "+f"(d[3])
        : "r"(a[0]), "r"(a[1]), "r"(a[2]), "r"(a[3]), "r"(b0), "r"(b1));
}

// =================== repack: fp16 fragment-order weights ===================
__global__ void repack_kernel(const float* __restrict__ prop_W2,
                              const float* __restrict__ ext_W2,
                              const float* __restrict__ opp_W2,
                              const float* __restrict__ pi_W1,
                              const float* __restrict__ pi_W2,
                              const float* __restrict__ pi_W3) {
    int idx = blockIdx.x * 256 + threadIdx.x;
    if (idx >= PK_TOTAL) return;
    int p = idx / PK_PLAYER;
    int r = idx - p * PK_PLAYER;
    unsigned o[4];
    if (r < PKP_PI1) {
        // enc: pass*2560 + warp*320 + c*160 + t*32 + lane ; t covers j = 2t, 2t+1
        int pass = r / 2560, e = r - pass * 2560;
        int warp = e / 320, e2 = e - warp * 320;
        int c = e2 / 160, e3 = e2 - c * 160;
        int t = e3 >> 5, lane = e3 & 31;
        int gr = lane >> 2, gc = lane & 3;
        #pragma unroll
        for (int q = 0; q < 4; q++) {
            int j = t * 2 + (q >> 1), b = q & 1;
            if (j > 8) { o[q] = 0; continue; }
            int col = warp * 72 + j * 8 + gr;           // 0..575
            int k = c * 16 + 2 * gc + b * 8;            // pair (k, k+1)
            float w0, w1;
            if (pass == 0) {
                int head = col >> 6, cc = col & 63;
                const float* W = prop_W2 + ((size_t)(p * 9 + head) * 32) * 64 + cc;
                w0 = W[(size_t)k * 64]; w1 = W[(size_t)(k + 1) * 64];
            } else if (pass == 1) {
                int head = (col >= 288) ? 1 : 0, cc = col - head * 288;
                const float* W = ext_W2 + ((size_t)(p * 2 + head) * 32) * 288 + cc;
                w0 = W[(size_t)k * 288]; w1 = W[(size_t)(k + 1) * 288];
            } else {
                const float* W = opp_W2 + ((size_t)p * 32) * 576 + col;
                w0 = W[(size_t)k * 576]; w1 = W[(size_t)(k + 1) * 576];
            }
            o[q] = pack_h2(w0, w1);
        }
    } else if (r < PKP_PI3) {
        int base;
        const float* W;
        if (r < PKP_PI2) { base = r - PKP_PI1; W = pi_W1 + (size_t)p * 147456; }
        else             { base = r - PKP_PI2; W = pi_W2 + (size_t)p * 65536; }
        int c = base / 512, e2 = base - c * 512;
        int nw = e2 >> 6, e3 = e2 & 63;
        int jp = e3 >> 5, lane = e3 & 31;
        int gr = lane >> 2, gc = lane & 3;
        #pragma unroll
        for (int q = 0; q < 4; q++) {
            int j = jp * 2 + (q >> 1), b = q & 1;
            int k = c * 16 + 2 * gc + b * 8;
            int n = nw * 32 + j * 8 + gr;
            o[q] = pack_h2(W[(size_t)k * 256 + n], W[(size_t)(k + 1) * 256 + n]);
        }
    } else {
        // pi3 (w3: [256][3]): cpair*32 + lane; float4 = chunks (2cp, 2cp+1) x (b0,b1)
        int e = r - PKP_PI3;
        int cp = e >> 5, lane = e & 31;
        int gr = lane >> 2, gc = lane & 3;
        const float* W = pi_W3 + (size_t)p * 768;
        #pragma unroll
        for (int q = 0; q < 4; q++) {
            int c = cp * 2 + (q >> 1), b = q & 1;
            int k = c * 16 + 2 * gc + b * 8;
            float w0 = 0.f, w1 = 0.f;
            if (gr < 3) { w0 = W[(size_t)k * 3 + gr]; w1 = W[(size_t)(k + 1) * 3 + gr]; }
            o[q] = pack_h2(w0, w1);
        }
    }
    g_pk4[idx] = make_float4(__uint_as_float(o[0]), __uint_as_float(o[1]),
                             __uint_as_float(o[2]), __uint_as_float(o[3]));
}

// =================== stage-1b fused: per j-tile, 3 passes in registers ===================
__device__ __forceinline__ void enc_all(const float* __restrict__ prop_b2,
                                        const float* __restrict__ ext_b2,
                                        const float* __restrict__ opp_b2,
                                        const float* smw, float* ef16,
                                        unsigned aad0, unsigned aad1,
                                        int warp, int lane, int p) {
    const int gr = lane >> 2, gc = lane & 3;
    const int cw = warp * 72;
    const float4* pk = g_pk4 + (size_t)p * PK_PLAYER + PKP_ENC + warp * 320 + lane;

    #pragma unroll
    for (int j = 0; j < 9; j++) {
        const int c0 = cw + j * 8;
        const int cb = c0 + 2 * gc;
        float sum[2][4];
        #pragma unroll
        for (int m = 0; m < 2; m++)
            #pragma unroll
            for (int u = 0; u < 4; u++) sum[m][u] = 0.f;

        #pragma unroll
        for (int pass = 0; pass < 3; pass++) {
            int abase, bidx0;
            if (pass == 0) { int head = c0 >> 6; abase = head * 16;
                             bidx0 = (p * 9 + head) * 64 + (cb & 63); }
            else if (pass == 1) { int head = (c0 >= 288) ? 1 : 0; abase = 144 + head * 16;
                             bidx0 = (p * 2 + head) * 288 + cb - head * 288; }
            else { abase = 176; bidx0 = p * 576 + cb; }
            const float* bias = (pass == 0) ? prop_b2 : (pass == 1) ? ext_b2 : opp_b2;

            float acc[2][4];
            #pragma unroll
            for (int m = 0; m < 2; m++)
                #pragma unroll
                for (int u = 0; u < 4; u++) acc[m][u] = 0.f;

            #pragma unroll
            for (int c = 0; c < 2; c++) {
                unsigned a0[4], a1[4];
                unsigned off = (abase + c * 8) * 4;
                LDSM4(a0, aad0 + off);
                LDSM4(a1, aad1 + off);
                float4 v = pk[pass * 2560 + c * 160 + (j >> 1) * 32];
                unsigned b0 = __float_as_uint((j & 1) ? v.z : v.x);
                unsigned b1 = __float_as_uint((j & 1) ? v.w : v.y);
                mma_f16(acc[0], a0, b0, b1);
                mma_f16(acc[1], a1, b0, b1);
            }
            float b0f = bias[bidx0], b1f = bias[bidx0 + 1];
            #pragma unroll
            for (int m = 0; m < 2; m++) {
                sum[m][0] += lrelu(acc[m][0] + b0f);
                sum[m][1] += lrelu(acc[m][1] + b1f);
                sum[m][2] += lrelu(acc[m][2] + b0f);
                sum[m][3] += lrelu(acc[m][3] + b1f);
            }
        }
        const int wc = (c0 >> 1) + gc;
        #pragma unroll
        for (int m = 0; m < 2; m++) {
            int rr = m * 16 + gr;
            ef16[(rr    ) * PE16W + wc] = __uint_as_float(pack_h2(sum[m][0], sum[m][1]));
            ef16[(rr + 8) * PE16W + wc] = __uint_as_float(pack_h2(sum[m][2], sum[m][3]));
        }
    }
}

// =================== pi GEMM: 8 n-warps, full K, LDSM A, depth-2 B prefetch ===================
// outputs fp16 words (h1/h2), pitch outPitch
template<int NCH, int PKOFF, int PAW>
__device__ __forceinline__ void pi_stage(const float* __restrict__ bias,
                                         const float* sAw, float* outp, int outPitch,
                                         int warp, int lane, int p) {
    const int n0 = warp * 32;
    const int gr = lane >> 2, gc = lane & 3;
    const float4* pk = g_pk4 + (size_t)p * PK_PLAYER + PKOFF + warp * 64 + lane;
    const unsigned aad0 = s2u(sAw + (lane & 15) * PAW + ((lane >> 4) << 2));
    const unsigned aad1 = s2u(sAw + (16 + (lane & 15)) * PAW + ((lane >> 4) << 2));

    float acc[2][4][4];
    #pragma unroll
    for (int m = 0; m < 2; m++)
        #pragma unroll
        for (int j = 0; j < 4; j++)
            #pragma unroll
            for (int u = 0; u < 4; u++) acc[m][j][u] = 0.f;

    float4 b0r[2], b1r[2];
    b0r[0] = pk[0];   b1r[0] = pk[32];
    b0r[1] = pk[512]; b1r[1] = pk[512 + 32];

    #pragma unroll 4
    for (int c = 0; c < NCH; c++) {
        float4 v0 = b0r[c & 1], v1 = b1r[c & 1];
        if (c + 2 < NCH) {
            b0r[c & 1] = pk[(c + 2) * 512];
            b1r[c & 1] = pk[(c + 2) * 512 + 32];
        }
        unsigned a0[4], a1[4];
        LDSM4(a0, aad0 + c * 32);
        LDSM4(a1, aad1 + c * 32);
        mma_f16(acc[0][0], a0, __float_as_uint(v0.x), __float_as_uint(v0.y));
        mma_f16(acc[0][1], a0, __float_as_uint(v0.z), __float_as_uint(v0.w));
        mma_f16(acc[0][2], a0, __float_as_uint(v1.x), __float_as_uint(v1.y));
        mma_f16(acc[0][3], a0, __float_as_uint(v1.z), __float_as_uint(v1.w));
        mma_f16(acc[1][0], a1, __float_as_uint(v0.x), __float_as_uint(v0.y));
        mma_f16(acc[1][1], a1, __float_as_uint(v0.z), __float_as_uint(v0.w));
        mma_f16(acc[1][2], a1, __float_as_uint(v1.x), __float_as_uint(v1.y));
        mma_f16(acc[1][3], a1, __float_as_uint(v1.z), __float_as_uint(v1.w));
    }

    #pragma unroll
    for (int m = 0; m < 2; m++) {
        int rr = m * 16 + gr;
        #pragma unroll
        for (int j = 0; j < 4; j++) {
            int cA = n0 + j * 8 + 2 * gc;
            float b0 = bias[cA], b1 = bias[cA + 1];
            float v00 = lrelu(acc[m][j][0] + b0), v01 = lrelu(acc[m][j][1] + b1);
            float v10 = lrelu(acc[m][j][2] + b0), v11 = lrelu(acc[m][j][3] + b1);
            int wc = cA >> 1;
            outp[(rr    ) * outPitch + wc] = __uint_as_float(pack_h2(v00, v01));
            outp[(rr + 8) * outPitch + wc] = __uint_as_float(pack_h2(v10, v11));
        }
    }
}

__global__ __launch_bounds__(THREADS, 3)
void mlpac_kernel(
    const float* __restrict__ obs,
    const float* __restrict__ prop_W1, const float* __restrict__ prop_b1,
    const float* __restrict__ prop_b2,
    const float* __restrict__ ext_W1,  const float* __restrict__ ext_b1,
    const float* __restrict__ ext_b2,
    const float* __restrict__ opp_W1,  const float* __restrict__ opp_b1,
    const float* __restrict__ opp_b2,
    const float* __restrict__ pi_b1,   const float* __restrict__ pi_b2,
    const float* __restrict__ pi_b3,
    float* __restrict__ out)
{
    extern __shared__ float sm[];
    float* s_hid  = sm + HID_OFF;    // fp16 words, pitch PHIDW
    float* s_ef16 = sm + EF16_OFF;   // fp16 words, pitch PE16W
    float* s_obs  = s_ef16;          // obs rows at pitch PE16W (dead after 1a)
    float* s_h1   = sm + HID_OFF;    // fp16 words, pitch PH1W (hid dead after 1b)
    float* s_h2   = sm + EF16_OFF;   // fp16 words, pitch PH1W (ef16 dead after stage2)

    const int tid  = threadIdx.x;
    const int warp = tid >> 5, lane = tid & 31;
    const int p    = blockIdx.y;
    const int b0   = blockIdx.x * TB;

    // ---------------- stage 0: obs ----------------
    for (int g = tid; g < TB * (OBSD / 4); g += THREADS) {
        int r = g / 12, q = g - r * 12;
        *(float4*)&s_obs[r * PE16W + q * 4] =
            *(const float4*)&obs[((size_t)(b0 + r) * NPLAYER + p) * OBSD + q * 4];
    }
    __syncthreads();

    // ---------------- stage 1a: hidden layers -> fp16 words in s_hid ----------------
    for (int i = tid; i < 32 * 9 * 16; i += THREADS) {
        int r = i / 144, rest = i - r * 144, n = rest >> 4, jw = rest & 15;
        const float* w = prop_W1 + ((p * 9 + n) * 2) * 32 + 2 * jw;
        float o0 = s_obs[r * PE16W + 2 * n], o1 = s_obs[r * PE16W + 2 * n + 1];
        const float* bb = prop_b1 + (p * 9 + n) * 32 + 2 * jw;
        float v0 = lrelu(o0 * w[0] + o1 * w[32] + bb[0]);
        float v1 = lrelu(o0 * w[1] + o1 * w[33] + bb[1]);
        s_hid[r * PHIDW + n * 16 + jw] = __uint_as_float(pack_h2(v0, v1));
    }
    for (int i = tid; i < 32 * 2 * 16; i += THREADS) {
        int r = i >> 5, rest = i & 31, n = rest >> 4, jw = rest & 15;
        const float* w = ext_W1 + ((p * 2 + n) * 6) * 32 + 2 * jw;
        const float* bb = ext_b1 + (p * 2 + n) * 32 + 2 * jw;
        float v0 = bb[0], v1 = bb[1];
        #pragma unroll
        for (int q = 0; q < 6; q++) {
            float o = s_obs[r * PE16W + 18 + n * 6 + q];
            v0 += o * w[q * 32]; v1 += o * w[q * 32 + 1];
        }
        s_hid[r * PHIDW + 144 + n * 16 + jw] = __uint_as_float(pack_h2(lrelu(v0), lrelu(v1)));
    }
    for (int i = tid; i < 32 * 16; i += THREADS) {
        int r = i >> 4, jw = i & 15;
        const float* w = opp_W1 + (p * 18) * 32 + 2 * jw;
        const float* bb = opp_b1 + p * 32 + 2 * jw;
        float v0 = bb[0], v1 = bb[1];
        #pragma unroll
        for (int q = 0; q < 18; q++) {
            float o = s_obs[r * PE16W + 30 + q];
            v0 += o * w[q * 32]; v1 += o * w[q * 32 + 1];
        }
        s_hid[r * PHIDW + 176 + jw] = __uint_as_float(pack_h2(lrelu(v0), lrelu(v1)));
    }
    __syncthreads();   // hid ready; obs (ef16 region) dead

    // ---------------- stage 1b: enc (fused 3 passes) ----------------
    {
        unsigned aad0 = s2u(s_hid + (lane & 15) * PHIDW + ((lane >> 4) << 2));
        unsigned aad1 = s2u(s_hid + (16 + (lane & 15)) * PHIDW + ((lane >> 4) << 2));
        enc_all(prop_b2, ext_b2, opp_b2, s_hid, s_ef16, aad0, aad1, warp, lane, p);
    }
    __syncthreads();   // ef16 ready; hid dead

    // ---------------- stage 2: h1 = lrelu(enc @ pi_W1 + b1) ----------------
    pi_stage<36, PKP_PI1, PE16W>(pi_b1 + p * 256, s_ef16, s_h1, PH1W, warp, lane, p);
    __syncthreads();   // h1 ready; ef16 dead

    // ---------------- stage 3: h2 = lrelu(h1 @ pi_W2 + b2) ----------------
    pi_stage<16, PKP_PI2, PH1W>(pi_b2 + p * 256, s_h1, s_h2, PH1W, warp, lane, p);
    __syncthreads();   // h2 ready

    // ---------------- stage 4: out = tanh(h2 @ pi_W3 + b3)  [1 warp, mma] ----------------
    if (warp == 0) {
        const int gr = lane >> 2, gc = lane & 3;
        const float4* pkw3 = g_pk4 + (size_t)p * PK_PLAYER + PKP_PI3;
        const unsigned aad0 = s2u(s_h2 + (lane & 15) * PH1W + ((lane >> 4) << 2));
        const unsigned aad1 = s2u(s_h2 + (16 + (lane & 15)) * PH1W + ((lane >> 4) << 2));
        float acc[2][4];
        #pragma unroll
        for (int m = 0; m < 2; m++)
            #pragma unroll
            for (int u = 0; u < 4; u++) acc[m][u] = 0.f;
        #pragma unroll
        for (int c = 0; c < 16; c++) {
            float4 v = pkw3[(c >> 1) * 32 + lane];
            unsigned b0 = __float_as_uint((c & 1) ? v.z : v.x);
            unsigned b1 = __float_as_uint((c & 1) ? v.w : v.y);
            unsigned a0[4], a1[4];
            LDSM4(a0, aad0 + c * 32);
            LDSM4(a1, aad1 + c * 32);
            mma_f16(acc[0], a0, b0, b1);
            mma_f16(acc[1], a1, b0, b1);
        }
        int c0 = 2 * gc, c1 = 2 * gc + 1;
        float bb0 = (c0 < 3) ? pi_b3[p * 3 + c0] : 0.f;
        float bb1 = (c1 < 3) ? pi_b3[p * 3 + c1] : 0.f;
        #pragma unroll
        for (int m = 0; m < 2; m++) {
            int r0 = m * 16 + gr, r1 = r0 + 8;
            if (c0 < 3) {
                out[((size_t)(b0 + r0) * NPLAYER + p) * 3 + c0] = tanhf(acc[m][0] + bb0);
                out[((size_t)(b0 + r1) * NPLAYER + p) * 3 + c0] = tanhf(acc[m][2] + bb0);
            }
            if (c1 < 3) {
                out[((size_t)(b0 + r0) * NPLAYER + p) * 3 + c1] = tanhf(acc[m][1] + bb1);
                out[((size_t)(b0 + r1) * NPLAYER + p) * 3 + c1] = tanhf(acc[m][3] + bb1);
            }
        }
    }
}

extern "C" void kernel_launch(void* const* d_in, const int* in_sizes, int n_in,
                              void* d_out, int out_size)
{
    (void)in_sizes; (void)n_in; (void)out_size;
    const float* obs     = (const float*)d_in[0];
    const float* prop_W1 = (const float*)d_in[1];
    const float* prop_b1 = (const float*)d_in[2];
    const float* prop_W2 = (const float*)d_in[3];
    const float* prop_b2 = (const float*)d_in[4];
    const float* ext_W1  = (const float*)d_in[5];
    const float* ext_b1  = (const float*)d_in[6];
    const float* ext_W2  = (const float*)d_in[7];
    const float* ext_b2  = (const float*)d_in[8];
    const float* opp_W1  = (const float*)d_in[9];
    const float* opp_b1  = (const float*)d_in[10];
    const float* opp_W2  = (const float*)d_in[11];
    const float* opp_b2  = (const float*)d_in[12];
    const float* pi_W1   = (const float*)d_in[13];
    const float* pi_b1   = (const float*)d_in[14];
    const float* pi_W2   = (const float*)d_in[15];
    const float* pi_b2   = (const float*)d_in[16];
    const float* pi_W3   = (const float*)d_in[17];
    const float* pi_b3   = (const float*)d_in[18];
    float* out = (float*)d_out;

    repack_kernel<<<(PK_TOTAL + 255) / 256, 256>>>(prop_W2, ext_W2, opp_W2,
                                                   pi_W1, pi_W2, pi_W3);

    const int smem_bytes = SMEM_WORDS * sizeof(float);
    cudaFuncSetAttribute(mlpac_kernel, cudaFuncAttributeMaxDynamicSharedMemorySize, smem_bytes);

    dim3 grid(BATCH / TB, NPLAYER);
    mlpac_kernel<<<grid, THREADS, smem_bytes>>>(
        obs, prop_W1, prop_b1, prop_b2,
        ext_W1, ext_b1, ext_b2,
        opp_W1, opp_b1, opp_b2,
        pi_b1, pi_b2, pi_b3, out);
}